// round 3
// baseline (speedup 1.0000x reference)
#include <cuda_runtime.h>
#include <cuda_bf16.h>

// Problem constants (from reference)
#define L_DIM  12
#define BS_DIM 2048          // B*S = 8*256
#define D_DIM  1024
#define N_DIM  2048
#define K_DIM  5
#define INV_TEMP 10.0f       // 1 / 0.1
#define EPS2 (1e-8f * 1e-8f) // eps^2 for rsqrt guard

#define WARPS_PER_BLOCK 8
#define ITEMS (L_DIM * N_DIM)            // 24576
#define NBLOCKS (ITEMS / WARPS_PER_BLOCK) // 3072
#define FINAL_SCALE (-1.0f / (float)(L_DIM * N_DIM))

__global__ void mi_zero_kernel(float* out) { *out = 0.0f; }

__device__ __forceinline__ float warp_allreduce(float v) {
    #pragma unroll
    for (int o = 16; o; o >>= 1) v += __shfl_xor_sync(0xFFFFFFFFu, v, o);
    return v;
}

// One warp handles one (l, n) item: 7 rows of 1024 floats.
__global__ void __launch_bounds__(WARPS_PER_BLOCK * 32)
mi_loss_kernel(const float* __restrict__ act,
               const int* __restrict__ aidx,
               const int* __restrict__ pidx,
               const int* __restrict__ nidx,
               float* __restrict__ out)
{
    const int warp = threadIdx.x >> 5;
    const int lane = threadIdx.x & 31;
    const int item = blockIdx.x * WARPS_PER_BLOCK + warp;
    const int l = item >> 11;        // / N_DIM
    const int n = item & (N_DIM - 1);

    const float* base = act + (size_t)l * (size_t)(BS_DIM * D_DIM);

    // Hoist all index loads up front (front-batch the small LDGs).
    const int ai = __ldg(&aidx[n]);
    const int pi = __ldg(&pidx[n]);
    int ni[K_DIM];
    #pragma unroll
    for (int k = 0; k < K_DIM; k++) ni[k] = __ldg(&nidx[n * K_DIM + k]);

    // ---- anchor row: cache in registers, compute |a|^2 ----
    const float4* arow = (const float4*)(base + (size_t)ai * D_DIM);
    float4 a[8];
    float asq = 0.0f;
    #pragma unroll
    for (int j = 0; j < 8; j++) {
        a[j] = __ldg(&arow[lane + j * 32]);
        asq += a[j].x * a[j].x + a[j].y * a[j].y
             + a[j].z * a[j].z + a[j].w * a[j].w;
    }
    asq = warp_allreduce(asq);
    const float inva = rsqrtf(fmaxf(asq, EPS2)); // == 1/max(||a||, eps)

    // ---- pos row ----
    float pos_sim;
    {
        const float4* row = (const float4*)(base + (size_t)pi * D_DIM);
        float dot = 0.0f, sq = 0.0f;
        #pragma unroll
        for (int j = 0; j < 8; j++) {
            float4 v = __ldg(&row[lane + j * 32]);
            dot += a[j].x * v.x + a[j].y * v.y + a[j].z * v.z + a[j].w * v.w;
            sq  += v.x * v.x + v.y * v.y + v.z * v.z + v.w * v.w;
        }
        dot = warp_allreduce(dot);
        sq  = warp_allreduce(sq);
        pos_sim = dot * inva * rsqrtf(fmaxf(sq, EPS2)) * INV_TEMP;
    }

    // ---- negatives ----
    float negsum = 0.0f;
    #pragma unroll
    for (int k = 0; k < K_DIM; k++) {
        const float4* row = (const float4*)(base + (size_t)ni[k] * D_DIM);
        float dot = 0.0f, sq = 0.0f;
        #pragma unroll
        for (int j = 0; j < 8; j++) {
            float4 v = __ldg(&row[lane + j * 32]);
            dot += a[j].x * v.x + a[j].y * v.y + a[j].z * v.z + a[j].w * v.w;
            sq  += v.x * v.x + v.y * v.y + v.z * v.z + v.w * v.w;
        }
        dot = warp_allreduce(dot);
        sq  = warp_allreduce(sq);
        float sim = dot * inva * rsqrtf(fmaxf(sq, EPS2)) * INV_TEMP;
        negsum += expf(sim);
    }

    // loss_n = pos_sim - log(exp(pos_sim) + sum_k exp(neg_k))
    const float loss = pos_sim - logf(expf(pos_sim) + negsum);

    // ---- block reduce (8 warp results) -> 1 atomic per block ----
    __shared__ float s_loss[WARPS_PER_BLOCK];
    if (lane == 0) s_loss[warp] = loss;
    __syncthreads();
    if (threadIdx.x == 0) {
        float t = 0.0f;
        #pragma unroll
        for (int w = 0; w < WARPS_PER_BLOCK; w++) t += s_loss[w];
        atomicAdd(out, t * FINAL_SCALE);
    }
}

extern "C" void kernel_launch(void* const* d_in, const int* in_sizes, int n_in,
                              void* d_out, int out_size)
{
    const float* act  = (const float*)d_in[0];
    const int*   aidx = (const int*)d_in[1];
    const int*   pidx = (const int*)d_in[2];
    const int*   nidx = (const int*)d_in[3];
    float* out = (float*)d_out;

    mi_zero_kernel<<<1, 1>>>(out);
    mi_loss_kernel<<<NBLOCKS, WARPS_PER_BLOCK * 32>>>(act, aidx, pidx, nidx, out);
}

// round 4
// speedup vs baseline: 1.0789x; 1.0789x over previous
#include <cuda_runtime.h>
#include <cuda_bf16.h>

// Problem constants (from reference)
#define L_DIM  12
#define BS_DIM 2048          // B*S = 8*256
#define D_DIM  1024
#define N_DIM  2048
#define K_DIM  5
#define INV_TEMP 10.0f       // 1 / 0.1
#define EPS2 (1e-8f * 1e-8f) // eps^2 for rsqrt guard

#define WARPS_PER_BLOCK 8
#define ITEMS (L_DIM * N_DIM)            // 24576
#define NBLOCKS (ITEMS / WARPS_PER_BLOCK) // 3072
#define FINAL_SCALE (-1.0f / (float)(L_DIM * N_DIM))

#define NROWS 6   // pos + 5 negatives

__global__ void mi_zero_kernel(float* out) { *out = 0.0f; }

__device__ __forceinline__ float warp_allreduce(float v) {
    #pragma unroll
    for (int o = 16; o; o >>= 1) v += __shfl_xor_sync(0xFFFFFFFFu, v, o);
    return v;
}

// One warp per (l, n) item. All 7 row-streams interleaved: each j-step
// issues 7 independent LDG.128s; all warp reductions deferred to the end.
__global__ void __launch_bounds__(WARPS_PER_BLOCK * 32, 3)
mi_loss_kernel(const float* __restrict__ act,
               const int* __restrict__ aidx,
               const int* __restrict__ pidx,
               const int* __restrict__ nidx,
               float* __restrict__ out)
{
    const int warp = threadIdx.x >> 5;
    const int lane = threadIdx.x & 31;
    const int item = blockIdx.x * WARPS_PER_BLOCK + warp;
    const int l = item >> 11;        // / N_DIM
    const int n = item & (N_DIM - 1);

    const float* base = act + (size_t)l * (size_t)(BS_DIM * D_DIM);

    // Front-batch the index loads.
    const int ai = __ldg(&aidx[n]);
    const int pi = __ldg(&pidx[n]);

    const float4* arow = (const float4*)(base + (size_t)ai * D_DIM);
    const float4* rows[NROWS];
    rows[0] = (const float4*)(base + (size_t)pi * D_DIM);
    #pragma unroll
    for (int k = 0; k < K_DIM; k++)
        rows[1 + k] = (const float4*)(base + (size_t)__ldg(&nidx[n * K_DIM + k]) * D_DIM);

    float asq = 0.0f;
    float dot[NROWS], sq[NROWS];
    #pragma unroll
    for (int r = 0; r < NROWS; r++) { dot[r] = 0.0f; sq[r] = 0.0f; }

    // 8 j-steps cover D=1024 (32 lanes x 8 x float4).
    #pragma unroll 2
    for (int j = 0; j < 8; j++) {
        const int off = lane + j * 32;
        const float4 av = __ldg(&arow[off]);
        float4 v[NROWS];
        #pragma unroll
        for (int r = 0; r < NROWS; r++) v[r] = __ldg(&rows[r][off]);

        asq += av.x * av.x + av.y * av.y + av.z * av.z + av.w * av.w;
        #pragma unroll
        for (int r = 0; r < NROWS; r++) {
            dot[r] += av.x * v[r].x + av.y * v[r].y
                    + av.z * v[r].z + av.w * v[r].w;
            sq[r]  += v[r].x * v[r].x + v[r].y * v[r].y
                    + v[r].z * v[r].z + v[r].w * v[r].w;
        }
    }

    // Deferred reductions: 13 independent SHFL chains (good ILP).
    asq = warp_allreduce(asq);
    #pragma unroll
    for (int r = 0; r < NROWS; r++) {
        dot[r] = warp_allreduce(dot[r]);
        sq[r]  = warp_allreduce(sq[r]);
    }

    const float inva = rsqrtf(fmaxf(asq, EPS2));

    const float pos_sim = dot[0] * inva * rsqrtf(fmaxf(sq[0], EPS2)) * INV_TEMP;
    float negsum = 0.0f;
    #pragma unroll
    for (int r = 1; r < NROWS; r++) {
        const float sim = dot[r] * inva * rsqrtf(fmaxf(sq[r], EPS2)) * INV_TEMP;
        negsum += expf(sim);
    }

    // loss_n = pos_sim - log(exp(pos_sim) + sum_k exp(neg_k))
    const float loss = pos_sim - logf(expf(pos_sim) + negsum);

    // ---- block reduce (8 warp results) -> 1 atomic per block ----
    __shared__ float s_loss[WARPS_PER_BLOCK];
    if (lane == 0) s_loss[warp] = loss;
    __syncthreads();
    if (threadIdx.x == 0) {
        float t = 0.0f;
        #pragma unroll
        for (int w = 0; w < WARPS_PER_BLOCK; w++) t += s_loss[w];
        atomicAdd(out, t * FINAL_SCALE);
    }
}

extern "C" void kernel_launch(void* const* d_in, const int* in_sizes, int n_in,
                              void* d_out, int out_size)
{
    const float* act  = (const float*)d_in[0];
    const int*   aidx = (const int*)d_in[1];
    const int*   pidx = (const int*)d_in[2];
    const int*   nidx = (const int*)d_in[3];
    float* out = (float*)d_out;

    mi_zero_kernel<<<1, 1>>>(out);
    mi_loss_kernel<<<NBLOCKS, WARPS_PER_BLOCK * 32>>>(act, aidx, pidx, nidx, out);
}

// round 6
// speedup vs baseline: 1.1777x; 1.0916x over previous
#include <cuda_runtime.h>
#include <cuda_bf16.h>

// Problem constants (from reference)
#define L_DIM  12
#define BS_DIM 2048          // B*S = 8*256
#define D_DIM  1024
#define N_DIM  2048
#define K_DIM  5
#define INV_TEMP 10.0f       // 1 / 0.1
#define EPS2 (1e-8f * 1e-8f) // eps^2 for rsqrt guard

#define WARPS_PER_BLOCK 8
#define ITEMS (L_DIM * N_DIM)            // 24576
#define NBLOCKS (ITEMS / WARPS_PER_BLOCK) // 3072
#define FINAL_SCALE (-1.0f / (float)(L_DIM * N_DIM))

#define NROWS 6   // pos + 5 negatives
#define ROW_F4 (D_DIM / 4)   // 256 float4 per row

__global__ void mi_zero_kernel(float* out) { *out = 0.0f; }

__device__ __forceinline__ float warp_allreduce(float v) {
    #pragma unroll
    for (int o = 16; o; o >>= 1) v += __shfl_xor_sync(0xFFFFFFFFu, v, o);
    return v;
}

// One warp per (l, n) item. 7 row-streams interleaved; 32-bit offsets from a
// single layer base keep register count under the 4-CTA/SM cap.
__global__ void __launch_bounds__(WARPS_PER_BLOCK * 32, 4)
mi_loss_kernel(const float* __restrict__ act,
               const int* __restrict__ aidx,
               const int* __restrict__ pidx,
               const int* __restrict__ nidx,
               float* __restrict__ out)
{
    const int warp = threadIdx.x >> 5;
    const int lane = threadIdx.x & 31;
    const int item = blockIdx.x * WARPS_PER_BLOCK + warp;
    const int l = item >> 11;        // / N_DIM
    const int n = item & (N_DIM - 1);

    // Single base pointer for this layer, all rows addressed by u32 offsets.
    const float4* __restrict__ base4 =
        (const float4*)(act + (size_t)l * (size_t)(BS_DIM * D_DIM));

    // Front-batch the index loads; build float4-unit offsets (fit in 32 bits).
    unsigned aoff = (unsigned)__ldg(&aidx[n]) * ROW_F4 + lane;
    unsigned roff[NROWS];
    roff[0] = (unsigned)__ldg(&pidx[n]) * ROW_F4 + lane;
    #pragma unroll
    for (int k = 0; k < K_DIM; k++)
        roff[1 + k] = (unsigned)__ldg(&nidx[n * K_DIM + k]) * ROW_F4 + lane;

    float asq = 0.0f;
    float dot[NROWS], sq[NROWS];
    #pragma unroll
    for (int r = 0; r < NROWS; r++) { dot[r] = 0.0f; sq[r] = 0.0f; }

    // 8 j-steps cover D=1024 (32 lanes x 8 x float4).
    #pragma unroll 1
    for (int j = 0; j < 8; j++) {
        const float4 av = __ldg(&base4[aoff]);
        float4 v[NROWS];
        #pragma unroll
        for (int r = 0; r < NROWS; r++) v[r] = __ldg(&base4[roff[r]]);

        aoff += 32;
        #pragma unroll
        for (int r = 0; r < NROWS; r++) roff[r] += 32;

        asq += av.x * av.x + av.y * av.y + av.z * av.z + av.w * av.w;
        #pragma unroll
        for (int r = 0; r < NROWS; r++) {
            dot[r] += av.x * v[r].x + av.y * v[r].y
                    + av.z * v[r].z + av.w * v[r].w;
            sq[r]  += v[r].x * v[r].x + v[r].y * v[r].y
                    + v[r].z * v[r].z + v[r].w * v[r].w;
        }
    }

    // Deferred reductions: 13 independent SHFL chains (good ILP).
    asq = warp_allreduce(asq);
    #pragma unroll
    for (int r = 0; r < NROWS; r++) {
        dot[r] = warp_allreduce(dot[r]);
        sq[r]  = warp_allreduce(sq[r]);
    }

    const float inva = rsqrtf(fmaxf(asq, EPS2));

    const float pos_sim = dot[0] * inva * rsqrtf(fmaxf(sq[0], EPS2)) * INV_TEMP;
    float negsum = 0.0f;
    #pragma unroll
    for (int r = 1; r < NROWS; r++) {
        const float sim = dot[r] * inva * rsqrtf(fmaxf(sq[r], EPS2)) * INV_TEMP;
        negsum += expf(sim);
    }

    // loss_n = pos_sim - log(exp(pos_sim) + sum_k exp(neg_k))
    const float loss = pos_sim - logf(expf(pos_sim) + negsum);

    // ---- block reduce (8 warp results) -> 1 atomic per block ----
    __shared__ float s_loss[WARPS_PER_BLOCK];
    if (lane == 0) s_loss[warp] = loss;
    __syncthreads();
    if (threadIdx.x == 0) {
        float t = 0.0f;
        #pragma unroll
        for (int w = 0; w < WARPS_PER_BLOCK; w++) t += s_loss[w];
        atomicAdd(out, t * FINAL_SCALE);
    }
}

extern "C" void kernel_launch(void* const* d_in, const int* in_sizes, int n_in,
                              void* d_out, int out_size)
{
    const float* act  = (const float*)d_in[0];
    const int*   aidx = (const int*)d_in[1];
    const int*   pidx = (const int*)d_in[2];
    const int*   nidx = (const int*)d_in[3];
    float* out = (float*)d_out;

    mi_zero_kernel<<<1, 1>>>(out);
    mi_loss_kernel<<<NBLOCKS, WARPS_PER_BLOCK * 32>>>(act, aidx, pidx, nidx, out);
}